// round 1
// baseline (speedup 1.0000x reference)
#include <cuda_runtime.h>

// Problem dims (fixed by the dataset)
#define BB 8
#define CC 19
#define HH 512
#define WW 1024
#define HWW (HH*WW)
#define NPIX (BB*HWW)

#define FLAGBIT 0x40000000
#define IDXMASK 0x3FFFFFFF

// ---------------- scratch (device globals; no allocation allowed) ----------
__device__ float          g_mag[NPIX];
__device__ unsigned char  g_sector[NPIX];
__device__ int            g_parent[NPIX];
__device__ unsigned char  g_wmask[NPIX];   // bit0=weak, bit1=strong, bit2=final edge
__device__ double         g_sum_nll;
__device__ double         g_sum_bnll;
__device__ unsigned long long g_cnt_valid;
__device__ unsigned long long g_cnt_b;

// ---------------- kernels --------------------------------------------------

__global__ void k_zero() {
    g_sum_nll = 0.0; g_sum_bnll = 0.0; g_cnt_valid = 0ULL; g_cnt_b = 0ULL;
}

// Sobel magnitude + quantized direction. img = (target*255) % 256, edge-pad.
__global__ __launch_bounds__(256) void k_mag(const int* __restrict__ tgt) {
    int i = blockIdx.x * blockDim.x + threadIdx.x;
    if (i >= NPIX) return;
    int b = i / HWW;
    int r = i - b * HWW;
    int h = r / WW;
    int w = r - h * WW;
    const int* timg = tgt + b * HWW;

#define IMGAT(hh, ww) ((float)((__ldg(timg + (min(max((hh),0),HH-1))*WW + (min(max((ww),0),WW-1))) * 255) & 255))
    float a00 = IMGAT(h-1, w-1), a01 = IMGAT(h-1, w), a02 = IMGAT(h-1, w+1);
    float a10 = IMGAT(h,   w-1),                      a12 = IMGAT(h,   w+1);
    float a20 = IMGAT(h+1, w-1), a21 = IMGAT(h+1, w), a22 = IMGAT(h+1, w+1);
#undef IMGAT

    float gx = (a02 + 2.f*a12 + a22) - (a00 + 2.f*a10 + a20);
    float gy = (a20 + 2.f*a21 + a22) - (a00 + 2.f*a01 + a02);
    float ax = fabsf(gx), ay = fabsf(gy);
    float mag = ax + ay;

    unsigned char sector;
    if (ay <= ax * 0.41421356f)      sector = 0;   // horiz -> compare left/right
    else if (ay >= ax * 2.41421356f) sector = 1;   // vert  -> compare up/down
    else sector = (gx * gy >= 0.f) ? 2 : 3;        // diagonals

    g_mag[i] = mag;
    g_sector[i] = sector;
}

// Non-max suppression + double threshold; init union-find parents.
__global__ __launch_bounds__(256) void k_nms() {
    int i = blockIdx.x * blockDim.x + threadIdx.x;
    if (i >= NPIX) return;
    int b = i / HWW;
    int r = i - b * HWW;
    int h = r / WW;
    int w = r - h * WW;
    const float* mimg = g_mag + b * HWW;

#define MAGAT(hh, ww) (((hh) < 0 || (hh) >= HH || (ww) < 0 || (ww) >= WW) ? 0.f : __ldg(mimg + (hh)*WW + (ww)))
    float mag = g_mag[i];
    int s = g_sector[i];
    float n1, n2;
    switch (s) {
        case 0:  n1 = MAGAT(h, w-1);   n2 = MAGAT(h, w+1);   break;
        case 1:  n1 = MAGAT(h-1, w);   n2 = MAGAT(h+1, w);   break;
        case 2:  n1 = MAGAT(h-1, w-1); n2 = MAGAT(h+1, w+1); break;
        default: n1 = MAGAT(h-1, w+1); n2 = MAGAT(h+1, w-1); break;
    }
#undef MAGAT
    bool keep = (mag >= n1) && (mag > n2);
    unsigned char m = 0;
    if (keep && mag > 50.f)  m |= 1;  // weak (includes strong)
    if (keep && mag > 150.f) m |= 2;  // strong
    g_wmask[i] = m;
    g_parent[i] = i;
}

__device__ __forceinline__ int uf_find(int* P, int x) {
    int p = P[x];
    while (p != x) {
        int gp = P[p];
        if (gp != p) P[x] = gp;  // path halving
        x = p; p = gp;
    }
    return x;
}

__device__ __forceinline__ void uf_union(int* P, int a, int b) {
    while (true) {
        a = uf_find(P, a);
        b = uf_find(P, b);
        if (a == b) return;
        if (a < b) { int t = a; a = b; b = t; }
        int old = atomicCAS(&P[a], a, b);
        if (old == a) return;
        a = old;
    }
}

// 8-connected merge over weak pixels (upper-half neighbors cover all edges).
__global__ __launch_bounds__(256) void k_merge() {
    int i = blockIdx.x * blockDim.x + threadIdx.x;
    if (i >= NPIX) return;
    if (!(g_wmask[i] & 1)) return;
    int b = i / HWW;
    int r = i - b * HWW;
    int h = r / WW;
    int w = r - h * WW;
    int base = b * HWW;

    // (0,-1), (-1,-1), (-1,0), (-1,1)
    if (w > 0) {
        int j = base + h * WW + (w - 1);
        if (g_wmask[j] & 1) uf_union(g_parent, i, j);
    }
    if (h > 0) {
        int rowup = base + (h - 1) * WW;
        if (w > 0)      { int j = rowup + (w - 1); if (g_wmask[j] & 1) uf_union(g_parent, i, j); }
        { int j = rowup + w; if (g_wmask[j] & 1) uf_union(g_parent, i, j); }
        if (w < WW - 1) { int j = rowup + (w + 1); if (g_wmask[j] & 1) uf_union(g_parent, i, j); }
    }
}

__global__ __launch_bounds__(256) void k_flatten() {
    int i = blockIdx.x * blockDim.x + threadIdx.x;
    if (i >= NPIX) return;
    g_parent[i] = uf_find(g_parent, i);
}

// Mark roots of components containing a strong pixel.
__global__ __launch_bounds__(256) void k_mark() {
    int i = blockIdx.x * blockDim.x + threadIdx.x;
    if (i >= NPIX) return;
    if (g_wmask[i] & 2) {
        int rt = g_parent[i] & IDXMASK;
        atomicOr(&g_parent[rt], FLAGBIT);
    }
}

// Resolve final edge mask + count boundary pixels.
__global__ __launch_bounds__(256) void k_bmask() {
    int i = blockIdx.x * blockDim.x + threadIdx.x;
    int edge = 0;
    if (i < NPIX) {
        unsigned char m = g_wmask[i];
        if (m & 1) {
            int rt = g_parent[i] & IDXMASK;
            edge = (g_parent[rt] & FLAGBIT) ? 1 : 0;
        }
        g_wmask[i] = (unsigned char)(m | (edge << 2));
    }
    int cnt = __syncthreads_count(edge);
    if (threadIdx.x == 0 && cnt > 0)
        atomicAdd(&g_cnt_b, (unsigned long long)cnt);
}

// Per-pixel cross-entropy (log_softmax over C=19) + masked accumulation.
__global__ __launch_bounds__(256) void k_nll(const float* __restrict__ in,
                                             const int* __restrict__ tgt) {
    int i = blockIdx.x * blockDim.x + threadIdx.x;
    float nll = 0.f;
    unsigned int validc = 0;
    int edge = 0;
    if (i < NPIX) {
        int t = tgt[i];
        bool valid = (t != 255);
        int b = i / HWW;
        int off = i - b * HWW;
        const float* base = in + (size_t)b * (CC * HWW) + off;
        float x[CC];
#pragma unroll
        for (int c = 0; c < CC; c++) x[c] = __ldg(base + (size_t)c * HWW);
        float mx = x[0];
#pragma unroll
        for (int c = 1; c < CC; c++) mx = fmaxf(mx, x[c]);
        float s = 0.f;
#pragma unroll
        for (int c = 0; c < CC; c++) s += __expf(x[c] - mx);
        int tt = (valid && t >= 0 && t < CC) ? t : 0;
        float v = mx + __logf(s) - x[tt];
        nll = valid ? v : 0.f;
        validc = valid ? 1u : 0u;
        edge = (g_wmask[i] >> 2) & 1;
    }

    // block reduction: sum_nll (double), sum_bnll (double), valid count
    double v1 = (double)nll;
    double v2 = edge ? (double)nll : 0.0;
    unsigned int cv = validc;
    const unsigned int full = 0xFFFFFFFFu;
#pragma unroll
    for (int o = 16; o > 0; o >>= 1) {
        v1 += __shfl_down_sync(full, v1, o);
        v2 += __shfl_down_sync(full, v2, o);
        cv += __shfl_down_sync(full, cv, o);
    }
    __shared__ double sh1[8], sh2[8];
    __shared__ unsigned int shc[8];
    int lane = threadIdx.x & 31, wid = threadIdx.x >> 5;
    if (lane == 0) { sh1[wid] = v1; sh2[wid] = v2; shc[wid] = cv; }
    __syncthreads();
    if (wid == 0) {
        v1 = (lane < 8) ? sh1[lane] : 0.0;
        v2 = (lane < 8) ? sh2[lane] : 0.0;
        cv = (lane < 8) ? shc[lane] : 0u;
#pragma unroll
        for (int o = 4; o > 0; o >>= 1) {
            v1 += __shfl_down_sync(full, v1, o);
            v2 += __shfl_down_sync(full, v2, o);
            cv += __shfl_down_sync(full, cv, o);
        }
        if (lane == 0) {
            atomicAdd(&g_sum_nll, v1);
            atomicAdd(&g_sum_bnll, v2);
            atomicAdd(&g_cnt_valid, (unsigned long long)cv);
        }
    }
}

__global__ void k_final(float* __restrict__ out) {
    unsigned long long cv = g_cnt_valid;
    unsigned long long cb = g_cnt_b;
    double ce = g_sum_nll / (double)(cv > 0 ? cv : 1ULL);
    double loss = ce;
    if (cb > 0) loss += 10.0 * (g_sum_bnll / (double)cb);
    out[0] = (float)loss;
}

// ---------------- launch ---------------------------------------------------

extern "C" void kernel_launch(void* const* d_in, const int* in_sizes, int n_in,
                              void* d_out, int out_size) {
    const float* input  = (const float*)d_in[0];
    const int*   target = (const int*)d_in[1];
    float* out = (float*)d_out;

    const int tb = 256;
    const int nb = (NPIX + tb - 1) / tb;

    k_zero<<<1, 1>>>();
    k_mag<<<nb, tb>>>(target);
    k_nms<<<nb, tb>>>();
    k_merge<<<nb, tb>>>();
    k_flatten<<<nb, tb>>>();
    k_mark<<<nb, tb>>>();
    k_bmask<<<nb, tb>>>();
    k_nll<<<nb, tb>>>(input, target);
    k_final<<<1, 1>>>(out);
}

// round 2
// speedup vs baseline: 1.3859x; 1.3859x over previous
#include <cuda_runtime.h>

// Problem dims (fixed by the dataset)
#define BB 8
#define CC 19
#define HH 512
#define WW 1024
#define HWW (HH*WW)
#define NPIX (BB*HWW)

// ---------------- scratch (device globals; no allocation allowed) ----------
__device__ int            g_parent[NPIX];
__device__ unsigned char  g_wmask[NPIX];   // bit0=weak, bit1=strong
__device__ unsigned char  g_flag[NPIX];    // root -> connected-to-strong
__device__ double         g_sum_nll;
__device__ double         g_sum_bnll;
__device__ unsigned long long g_cnt_valid;
__device__ unsigned long long g_cnt_b;

// ================= fused Sobel + NMS + threshold ===========================
// tile 16(h) x 64(w), 256 threads, 4 px/thread
#define MT_H 16
#define MT_W 64

__global__ __launch_bounds__(256) void k_magnms(const int* __restrict__ tgt) {
    __shared__ float simg[MT_H + 4][MT_W + 4];   // img with halo 2, edge-clamped
    __shared__ float smag[MT_H + 2][MT_W + 2];   // mag with halo 1, 0 outside img

    const int tid = threadIdx.x;
    const int b  = blockIdx.z;
    const int h0 = blockIdx.y * MT_H;
    const int w0 = blockIdx.x * MT_W;
    const int* timg = tgt + b * HWW;

    if (blockIdx.x == 0 && blockIdx.y == 0 && blockIdx.z == 0 && tid == 0) {
        g_sum_nll = 0.0; g_sum_bnll = 0.0; g_cnt_valid = 0ULL; g_cnt_b = 0ULL;
    }

    // load image (target*255)%256, edge padded
    for (int l = tid; l < (MT_H + 4) * (MT_W + 4); l += 256) {
        int rr = l / (MT_W + 4), cc = l - rr * (MT_W + 4);
        int gh = min(max(h0 - 2 + rr, 0), HH - 1);
        int gw = min(max(w0 - 2 + cc, 0), WW - 1);
        int t = __ldg(timg + gh * WW + gw);
        simg[rr][cc] = (float)((t * 255) & 255);
    }
    __syncthreads();

    // mag with halo 1 (0 outside image bounds -> matches zero-padded NMS)
    for (int l = tid; l < (MT_H + 2) * (MT_W + 2); l += 256) {
        int r = l / (MT_W + 2), c = l - r * (MT_W + 2);
        int gh = h0 - 1 + r, gw = w0 - 1 + c;
        float m = 0.f;
        if (gh >= 0 && gh < HH && gw >= 0 && gw < WW) {
            float a00 = simg[r][c],     a01 = simg[r][c+1],     a02 = simg[r][c+2];
            float a10 = simg[r+1][c],                           a12 = simg[r+1][c+2];
            float a20 = simg[r+2][c],   a21 = simg[r+2][c+1],   a22 = simg[r+2][c+2];
            float gx = (a02 + 2.f*a12 + a22) - (a00 + 2.f*a10 + a20);
            float gy = (a20 + 2.f*a21 + a22) - (a00 + 2.f*a01 + a02);
            m = fabsf(gx) + fabsf(gy);
        }
        smag[r][c] = m;
    }
    __syncthreads();

    // NMS + double threshold; 4 consecutive pixels per thread
    int l0 = tid * 4;
    int lr = l0 / MT_W, lcb = l0 - lr * MT_W;
    uchar4 mout;
    unsigned char* mo = (unsigned char*)&mout;
#pragma unroll
    for (int k = 0; k < 4; k++) {
        int lc = lcb + k;
        // recompute gradient direction for the center pixel
        int r = lr + 1, c = lc + 1;   // in smag coords; simg center = [lr+2][lc+2]
        float a00 = simg[lr+1][lc+1], a01 = simg[lr+1][lc+2], a02 = simg[lr+1][lc+3];
        float a10 = simg[lr+2][lc+1],                         a12 = simg[lr+2][lc+3];
        float a20 = simg[lr+3][lc+1], a21 = simg[lr+3][lc+2], a22 = simg[lr+3][lc+3];
        float gx = (a02 + 2.f*a12 + a22) - (a00 + 2.f*a10 + a20);
        float gy = (a20 + 2.f*a21 + a22) - (a00 + 2.f*a01 + a02);
        float ax = fabsf(gx), ay = fabsf(gy);
        float mag = smag[r][c];
        float n1, n2;
        if (ay <= ax * 0.41421356f)      { n1 = smag[r][c-1];   n2 = smag[r][c+1]; }
        else if (ay >= ax * 2.41421356f) { n1 = smag[r-1][c];   n2 = smag[r+1][c]; }
        else if (gx * gy >= 0.f)         { n1 = smag[r-1][c-1]; n2 = smag[r+1][c+1]; }
        else                             { n1 = smag[r-1][c+1]; n2 = smag[r+1][c-1]; }
        bool keep = (mag >= n1) && (mag > n2);
        unsigned char m = 0;
        if (keep && mag > 50.f)  m |= 1;
        if (keep && mag > 150.f) m |= 2;
        mo[k] = m;
    }
    int gidx = b * HWW + (h0 + lr) * WW + w0 + lcb;
    *(uchar4*)(g_wmask + gidx) = mout;
    *(uchar4*)(g_flag  + gidx) = make_uchar4(0, 0, 0, 0);
}

// ================= tile-local union-find (shared memory) ===================
#define TS 32   // 32x32 tile = 1024 px, 256 threads x 4

__device__ __forceinline__ int find_s(int* sp, int x) {
    int p = sp[x];
    while (p != x) {
        int gp = sp[p];
        if (gp != p) sp[x] = gp;
        x = p; p = gp;
    }
    return x;
}

__device__ __forceinline__ void union_s(int* sp, int a, int b) {
    while (true) {
        a = find_s(sp, a);
        b = find_s(sp, b);
        if (a == b) return;
        if (a < b) { int t = a; a = b; b = t; }
        int old = atomicCAS(&sp[a], a, b);
        if (old == a) return;
        a = old;
    }
}

__global__ __launch_bounds__(256) void k_local() {
    __shared__ int sp[TS * TS];
    __shared__ unsigned char lw[TS * TS];

    const int tid = threadIdx.x;
    const int b  = blockIdx.z;
    const int h0 = blockIdx.y * TS;
    const int w0 = blockIdx.x * TS;
    const int base = b * HWW;

#pragma unroll
    for (int k = 0; k < 4; k++) {
        int l = tid * 4 + k;
        sp[l] = l;
    }
    {
        int l = tid * 4;
        int lr = l >> 5, lc = l & 31;
        uchar4 w4 = *(const uchar4*)(g_wmask + base + (h0 + lr) * WW + w0 + lc);
        *(uchar4*)(lw + l) = w4;
    }
    __syncthreads();

#pragma unroll
    for (int k = 0; k < 4; k++) {
        int l = tid * 4 + k;
        if (!(lw[l] & 1)) continue;
        int lr = l >> 5, lc = l & 31;
        if (lc > 0 && (lw[l - 1] & 1)) union_s(sp, l, l - 1);
        if (lr > 0) {
            if (lw[l - 32] & 1)              union_s(sp, l, l - 32);
            if (lc > 0  && (lw[l - 33] & 1)) union_s(sp, l, l - 33);
            if (lc < 31 && (lw[l - 31] & 1)) union_s(sp, l, l - 31);
        }
    }
    __syncthreads();

#pragma unroll
    for (int k = 0; k < 4; k++) {
        int l = tid * 4 + k;
        if (!(lw[l] & 1)) continue;
        int root = find_s(sp, l);
        int lr = l >> 5, lc = l & 31;
        int groot = base + (h0 + (root >> 5)) * WW + (w0 + (root & 31));
        g_parent[base + (h0 + lr) * WW + w0 + lc] = groot;
    }
}

// ================= cross-tile border unions ================================
__device__ __forceinline__ int uf_find(int* P, int x) {
    int p = P[x];
    while (p != x) {
        int gp = P[p];
        if (gp != p) P[x] = gp;
        x = p; p = gp;
    }
    return x;
}

__device__ __forceinline__ void uf_union(int* P, int a, int b) {
    while (true) {
        a = uf_find(P, a);
        b = uf_find(P, b);
        if (a == b) return;
        if (a < b) { int t = a; a = b; b = t; }
        int old = atomicCAS(&P[a], a, b);
        if (old == a) return;
    a = old;
    }
}

__global__ __launch_bounds__(256) void k_border() {
    int i = blockIdx.x * blockDim.x + threadIdx.x;
    if (i >= NPIX) return;
    int b = i / HWW;
    int r = i - b * HWW;
    int h = r / WW;
    int w = r - h * WW;
    int lr = h & (TS - 1), lc = w & (TS - 1);
    if (lr != 0 && lc != 0 && lc != TS - 1) return;
    if (!(g_wmask[i] & 1)) return;
    int base = b * HWW;

    if (lc == 0 && w > 0) {                       // left crosses tile
        int j = base + h * WW + (w - 1);
        if (g_wmask[j] & 1) uf_union(g_parent, i, j);
    }
    if (h > 0) {
        int rowup = base + (h - 1) * WW;
        if (lr == 0 && (g_wmask[rowup + w] & 1))  // up crosses tile
            uf_union(g_parent, i, rowup + w);
        if ((lr == 0 || lc == 0) && w > 0) {      // up-left crosses tile
            int j = rowup + (w - 1);
            if (g_wmask[j] & 1) uf_union(g_parent, i, j);
        }
        if ((lr == 0 || lc == TS - 1) && w < WW - 1) {  // up-right crosses tile
            int j = rowup + (w + 1);
            if (g_wmask[j] & 1) uf_union(g_parent, i, j);
        }
    }
}

// ================= flatten (weak only) + mark strong roots =================
__global__ __launch_bounds__(256) void k_flatmark() {
    int i = blockIdx.x * blockDim.x + threadIdx.x;
    if (i >= NPIX) return;
    unsigned char m = g_wmask[i];
    if (!(m & 1)) return;
    int root = uf_find(g_parent, i);
    g_parent[i] = root;
    if (m & 2) g_flag[root] = 1;
}

// ================= fused NLL + edge resolve + reduction ====================
__global__ __launch_bounds__(256) void k_nll(const float* __restrict__ in,
                                             const int* __restrict__ tgt) {
    const int tid = threadIdx.x;
    int p0 = (blockIdx.x * 256 + tid) * 4;          // 4 consecutive pixels
    int b = p0 / HWW;
    int off = p0 - b * HWW;
    const float* basep = in + (size_t)b * (CC * HWW) + off;

    int4 t4 = *(const int4*)(tgt + p0);
    int tg[4] = {t4.x, t4.y, t4.z, t4.w};

    float mx[4] = {-1e30f, -1e30f, -1e30f, -1e30f};
    float s[4]  = {0.f, 0.f, 0.f, 0.f};
    float xt[4] = {0.f, 0.f, 0.f, 0.f};
#pragma unroll
    for (int c = 0; c < CC; c++) {
        float4 f = *(const float4*)(basep + (size_t)c * HWW);
        float xv[4] = {f.x, f.y, f.z, f.w};
#pragma unroll
        for (int k = 0; k < 4; k++) {
            float nm = fmaxf(mx[k], xv[k]);
            s[k] = s[k] * __expf(mx[k] - nm) + __expf(xv[k] - nm);
            mx[k] = nm;
            if (c == tg[k]) xt[k] = xv[k];
        }
    }

    uchar4 m4 = *(const uchar4*)(g_wmask + p0);
    unsigned char mm[4] = {m4.x, m4.y, m4.z, m4.w};

    double v1 = 0.0, v2 = 0.0;
    unsigned int cv = 0, cb = 0;
#pragma unroll
    for (int k = 0; k < 4; k++) {
        bool valid = (tg[k] != 255);
        float nll = valid ? (mx[k] + __logf(s[k]) - xt[k]) : 0.f;
        int edge = 0;
        if (mm[k] & 1) edge = g_flag[g_parent[p0 + k]];
        v1 += (double)nll;
        if (edge) { v2 += (double)nll; cb++; }
        cv += valid ? 1u : 0u;
    }

    const unsigned int full = 0xFFFFFFFFu;
#pragma unroll
    for (int o = 16; o > 0; o >>= 1) {
        v1 += __shfl_down_sync(full, v1, o);
        v2 += __shfl_down_sync(full, v2, o);
        cv += __shfl_down_sync(full, cv, o);
        cb += __shfl_down_sync(full, cb, o);
    }
    __shared__ double sh1[8], sh2[8];
    __shared__ unsigned int shc[8], shb[8];
    int lane = tid & 31, wid = tid >> 5;
    if (lane == 0) { sh1[wid] = v1; sh2[wid] = v2; shc[wid] = cv; shb[wid] = cb; }
    __syncthreads();
    if (wid == 0) {
        v1 = (lane < 8) ? sh1[lane] : 0.0;
        v2 = (lane < 8) ? sh2[lane] : 0.0;
        cv = (lane < 8) ? shc[lane] : 0u;
        cb = (lane < 8) ? shb[lane] : 0u;
#pragma unroll
        for (int o = 4; o > 0; o >>= 1) {
            v1 += __shfl_down_sync(full, v1, o);
            v2 += __shfl_down_sync(full, v2, o);
            cv += __shfl_down_sync(full, cv, o);
            cb += __shfl_down_sync(full, cb, o);
        }
        if (lane == 0) {
            atomicAdd(&g_sum_nll, v1);
            atomicAdd(&g_sum_bnll, v2);
            atomicAdd(&g_cnt_valid, (unsigned long long)cv);
            atomicAdd(&g_cnt_b, (unsigned long long)cb);
        }
    }
}

__global__ void k_final(float* __restrict__ out) {
    unsigned long long cv = g_cnt_valid;
    unsigned long long cb = g_cnt_b;
    double ce = g_sum_nll / (double)(cv > 0 ? cv : 1ULL);
    double loss = ce;
    if (cb > 0) loss += 10.0 * (g_sum_bnll / (double)cb);
    out[0] = (float)loss;
}

// ---------------- launch ---------------------------------------------------

extern "C" void kernel_launch(void* const* d_in, const int* in_sizes, int n_in,
                              void* d_out, int out_size) {
    const float* input  = (const float*)d_in[0];
    const int*   target = (const int*)d_in[1];
    float* out = (float*)d_out;

    const int tb = 256;
    const int nb = (NPIX + tb - 1) / tb;

    k_magnms<<<dim3(WW / MT_W, HH / MT_H, BB), 256>>>(target);
    k_local<<<dim3(WW / TS, HH / TS, BB), 256>>>();
    k_border<<<nb, tb>>>();
    k_flatmark<<<nb, tb>>>();
    k_nll<<<NPIX / 4 / 256, 256>>>(input, target);
    k_final<<<1, 1>>>(out);
}